// round 16
// baseline (speedup 1.0000x reference)
#include <cuda_runtime.h>
#include <mma.h>

using namespace nvcuda;

// Problem constants (dataset-fixed shapes)
#define F_IN   128
#define F_OUT  64
#define MAX_N  50000
#define MAX_E  800000

// ---------------- static scratch (no allocs allowed) ----------------
__device__ __align__(16) float g_support[MAX_N * F_OUT]; // (x@W)*t
__device__ __align__(16) int2  g_edges[MAX_E];           // (src, ev bits) bucketed by dst
__device__ __align__(16) int g_count[MAX_N];             // per-dst degree
__device__ __align__(16) int g_eoff[MAX_N];              // exclusive offsets
__device__ __align__(16) int g_cursor[MAX_N];            // fill cursors
__device__ int g_bsum[64];                               // scan block totals
__device__ int g_idx_is64;                               // index dtype flag

// ---------------------------------------------------------------------------
// K0: zero counts + detect index dtype in one launch.
// int32 buffers read as int64 give values >= 2^32 almost surely.
// ---------------------------------------------------------------------------
__global__ void detect_zero_kernel(const long long* __restrict__ src64,
                                   int n, int e)
{
    int i = blockIdx.x * blockDim.x + threadIdx.x;
    if (i < n) g_count[i] = 0;
    if (blockIdx.x == 0 && threadIdx.x < 32) {
        int cnt = (e < 32) ? e : 32;
        bool bad = false;
        if ((int)threadIdx.x < cnt) {
            long long v = src64[threadIdx.x];
            bad = (v < 0 || v >= (long long)n);
        }
        unsigned m = __ballot_sync(0xffffffffu, bad);
        if (threadIdx.x == 0) g_idx_is64 = (m == 0u) ? 1 : 0;
    }
}

__device__ __forceinline__ int load_idx(const void* p, int i)
{
    return g_idx_is64 ? (int)((const long long*)p)[i] : ((const int*)p)[i];
}

// ---------------------------------------------------------------------------
// K1 (side stream): tensor-core GEMM + row scale (3xTF32 for fp32 accuracy).
// support[r,:] = (x[r,:] @ W) * t[r]
// Block: 256 threads / 8 warps; tile 64 rows x 64 cols.
// Warp w: m0 = (w>>1)*16, n0 = (w&1)*32  (two 16x16 n-tiles).
// K = 128 in two halves of 64 staged through smem.
// 3xTF32: a = a_hi + a_lo, b = b_hi + b_lo; acc += a_hi*b_hi + a_hi*b_lo + a_lo*b_hi.
// ---------------------------------------------------------------------------
__global__ void __launch_bounds__(256)
gemm_tf32_kernel(const float* __restrict__ x,
                 const float* __restrict__ w,
                 const float* __restrict__ t,
                 int n)
{
    __shared__ float xs[64 * 72];     // 18.4 KB  x tile (stride 72)
    __shared__ float ws[64 * 64];     // 16 KB    W K-half

    const int tid  = threadIdx.x;
    const int warp = tid >> 5;
    const int row0 = blockIdx.x * 64;
    const int m0 = (warp >> 1) * 16;
    const int n0 = (warp & 1) * 32;

    wmma::fragment<wmma::accumulator, 16, 16, 8, float> acc[2];
    wmma::fill_fragment(acc[0], 0.0f);
    wmma::fill_fragment(acc[1], 0.0f);

    #pragma unroll
    for (int half = 0; half < 2; half++) {
        __syncthreads();
        // W half: 64x64 floats = 1024 float4, 4 per thread
        {
            const float4* s = (const float4*)(w + half * 64 * F_OUT);
            float4* d = (float4*)ws;
            #pragma unroll
            for (int i = 0; i < 4; i++) d[tid + i * 256] = s[tid + i * 256];
        }
        // x tile: 64 rows x 64 cols
        #pragma unroll
        for (int i = 0; i < 4; i++) {
            int f = tid + i * 256;
            int r = f >> 4, k4 = f & 15;
            int grow = row0 + r;
            float4 v = make_float4(0.f, 0.f, 0.f, 0.f);
            if (grow < n)
                v = *(const float4*)(x + (long long)grow * F_IN + half * 64 + k4 * 4);
            float* dd = xs + r * 72 + k4 * 4;
            dd[0] = v.x; dd[1] = v.y; dd[2] = v.z; dd[3] = v.w;
        }
        __syncthreads();

        #pragma unroll
        for (int s = 0; s < 8; s++) {
            int k0 = s * 8;
            wmma::fragment<wmma::matrix_a, 16, 16, 8, wmma::precision::tf32, wmma::row_major> a_raw, a_hi, a_lo;
            wmma::load_matrix_sync(a_raw, xs + m0 * 72 + k0, 72);
            #pragma unroll
            for (int i = 0; i < a_raw.num_elements; i++) {
                float v  = a_raw.x[i];
                float hi = wmma::__float_to_tf32(v);
                a_hi.x[i] = hi;
                a_lo.x[i] = wmma::__float_to_tf32(v - hi);
            }
            #pragma unroll
            for (int j = 0; j < 2; j++) {
                wmma::fragment<wmma::matrix_b, 16, 16, 8, wmma::precision::tf32, wmma::row_major> b_raw, b_hi, b_lo;
                wmma::load_matrix_sync(b_raw, ws + k0 * 64 + n0 + j * 16, 64);
                #pragma unroll
                for (int i = 0; i < b_raw.num_elements; i++) {
                    float v  = b_raw.x[i];
                    float hi = wmma::__float_to_tf32(v);
                    b_hi.x[i] = hi;
                    b_lo.x[i] = wmma::__float_to_tf32(v - hi);
                }
                wmma::mma_sync(acc[j], a_hi, b_hi, acc[j]);
                wmma::mma_sync(acc[j], a_hi, b_lo, acc[j]);
                wmma::mma_sync(acc[j], a_lo, b_hi, acc[j]);
            }
        }
    }

    // Epilogue: stage 64x64 fp32 tile in smem (stride 68), scale rows by t, write.
    __syncthreads();
    float* es = xs;   // reuse (64*68 = 17.4 KB <= 18.4 KB)
    wmma::store_matrix_sync(es + m0 * 68 + n0,      acc[0], 68, wmma::mem_row_major);
    wmma::store_matrix_sync(es + m0 * 68 + n0 + 16, acc[1], 68, wmma::mem_row_major);
    __syncthreads();

    #pragma unroll
    for (int i = 0; i < 4; i++) {
        int f = tid + i * 256;
        int r = f >> 4, c4 = f & 15;
        int grow = row0 + r;
        if (grow < n) {
            float tv = t[grow];
            float4 v = *(const float4*)(es + r * 68 + c4 * 4);
            v.x *= tv; v.y *= tv; v.z *= tv; v.w *= tv;
            *(float4*)(g_support + (long long)grow * F_OUT + c4 * 4) = v;
        }
    }
}

// ---------------------------------------------------------------------------
// K2: per-dst histogram, 4 edges/thread with vector index loads (MLP=4)
// ---------------------------------------------------------------------------
__global__ void __launch_bounds__(256)
hist_kernel(const void* __restrict__ dst, int e)
{
    int base = (blockIdx.x * blockDim.x + threadIdx.x) << 2;
    if (base >= e) return;
    int rem = e - base;

    int d0, d1 = -1, d2 = -1, d3 = -1;
    if (rem >= 4) {
        if (g_idx_is64) {
            const longlong2* p = (const longlong2*)((const long long*)dst + base);
            longlong2 a = p[0], b = p[1];
            d0 = (int)a.x; d1 = (int)a.y; d2 = (int)b.x; d3 = (int)b.y;
        } else {
            int4 v = *(const int4*)((const int*)dst + base);
            d0 = v.x; d1 = v.y; d2 = v.z; d3 = v.w;
        }
    } else {
        d0 = load_idx(dst, base);
        if (rem > 1) d1 = load_idx(dst, base + 1);
        if (rem > 2) d2 = load_idx(dst, base + 2);
    }

    atomicAdd(&g_count[d0], 1);
    if (d1 >= 0) atomicAdd(&g_count[d1], 1);
    if (d2 >= 0) atomicAdd(&g_count[d2], 1);
    if (d3 >= 0) atomicAdd(&g_count[d3], 1);
}

// ---------------------------------------------------------------------------
// K3: block scan (256 threads x 4 items = 1024 per block), shfl-based.
// ---------------------------------------------------------------------------
__global__ void __launch_bounds__(256)
scan1_kernel(int n)
{
    __shared__ int wsum[8];
    int t = threadIdx.x;
    int gi = blockIdx.x * 1024 + t * 4;

    int4 c = make_int4(0, 0, 0, 0);
    if (gi + 3 < n) {
        c = *(const int4*)&g_count[gi];
    } else if (gi < n) {
        c.x = g_count[gi];
        if (gi + 1 < n) c.y = g_count[gi + 1];
        if (gi + 2 < n) c.z = g_count[gi + 2];
    }
    int s3 = c.x + c.y + c.z + c.w;

    int lane = t & 31, wid = t >> 5;
    int ws = s3;
    #pragma unroll
    for (int off = 1; off < 32; off <<= 1) {
        int u = __shfl_up_sync(0xffffffffu, ws, off);
        if (lane >= off) ws += u;
    }
    if (lane == 31) wsum[wid] = ws;
    __syncthreads();
    if (t == 0) {
        int run = 0;
        #pragma unroll
        for (int j = 0; j < 8; j++) { int v = wsum[j]; wsum[j] = run; run += v; }
        g_bsum[blockIdx.x] = run;
    }
    __syncthreads();

    int excl = wsum[wid] + (ws - s3);
    if (gi < n) {
        g_eoff[gi] = excl;
        if (gi + 1 < n) g_eoff[gi + 1] = excl + c.x;
        if (gi + 2 < n) g_eoff[gi + 2] = excl + c.x + c.y;
        if (gi + 3 < n) g_eoff[gi + 3] = excl + c.x + c.y + c.z;
    }
}

// ---------------------------------------------------------------------------
// K4: add block offsets (each block reduces its own prefix from g_bsum)
// and initialize cursors.
// ---------------------------------------------------------------------------
__global__ void __launch_bounds__(256)
scan3_kernel(int n)
{
    __shared__ int s_off;
    int chunk = blockIdx.x >> 2;
    if (threadIdx.x < 32) {
        int v = 0;
        for (int j = (int)threadIdx.x; j < chunk; j += 32) v += g_bsum[j];
        #pragma unroll
        for (int off = 16; off; off >>= 1)
            v += __shfl_down_sync(0xffffffffu, v, off);
        if (threadIdx.x == 0) s_off = v;
    }
    __syncthreads();
    int i = blockIdx.x * 256 + threadIdx.x;
    if (i < n) {
        int e0 = g_eoff[i] + s_off;
        g_eoff[i]   = e0;
        g_cursor[i] = e0;
    }
}

// ---------------------------------------------------------------------------
// K5: bucket edges by dst, 4 edges/thread, vector loads.
// ---------------------------------------------------------------------------
__global__ void __launch_bounds__(256)
reorder_kernel(const void* __restrict__ src,
               const void* __restrict__ dst,
               const float* __restrict__ ev,
               int e)
{
    int base = (blockIdx.x * blockDim.x + threadIdx.x) << 2;
    if (base >= e) return;
    int rem = e - base;

    int s[4], d[4];
    float v[4];
    int cnt;
    if (rem >= 4) {
        cnt = 4;
        if (g_idx_is64) {
            const longlong2* ps = (const longlong2*)((const long long*)src + base);
            const longlong2* pd = (const longlong2*)((const long long*)dst + base);
            longlong2 a = ps[0], b = ps[1];
            longlong2 c = pd[0], f = pd[1];
            s[0] = (int)a.x; s[1] = (int)a.y; s[2] = (int)b.x; s[3] = (int)b.y;
            d[0] = (int)c.x; d[1] = (int)c.y; d[2] = (int)f.x; d[3] = (int)f.y;
        } else {
            int4 a = *(const int4*)((const int*)src + base);
            int4 c = *(const int4*)((const int*)dst + base);
            s[0] = a.x; s[1] = a.y; s[2] = a.z; s[3] = a.w;
            d[0] = c.x; d[1] = c.y; d[2] = c.z; d[3] = c.w;
        }
        float4 vv = *(const float4*)(ev + base);
        v[0] = vv.x; v[1] = vv.y; v[2] = vv.z; v[3] = vv.w;
    } else {
        cnt = rem;
        for (int j = 0; j < rem; j++) {
            s[j] = load_idx(src, base + j);
            d[j] = load_idx(dst, base + j);
            v[j] = ev[base + j];
        }
    }

    #pragma unroll
    for (int j = 0; j < 4; j++) {
        if (j < cnt) {
            int pos = atomicAdd(&g_cursor[d[j]], 1);
            g_edges[pos] = make_int2(s[j], __float_as_int(v[j]));
        }
    }
}

// ---------------------------------------------------------------------------
// K6: gather-reduce. One warp per dst node; lane owns 2 cols (float2).
// out[d,:] = sum_e ev_e * support[src_e,:] + bias. No atomics.
// ---------------------------------------------------------------------------
__global__ void __launch_bounds__(256)
gather_kernel(float* __restrict__ out,
              const float* __restrict__ bias,
              int n)
{
    int node = blockIdx.x * 8 + (threadIdx.x >> 5);
    if (node >= n) return;
    int lane = threadIdx.x & 31;

    int start = g_eoff[node];
    int deg   = g_count[node];

    float2 acc = *(const float2*)(bias + lane * 2);

    int j = 0;
    for (; j + 3 < deg; j += 4) {
        int2 r0 = g_edges[start + j];
        int2 r1 = g_edges[start + j + 1];
        int2 r2 = g_edges[start + j + 2];
        int2 r3 = g_edges[start + j + 3];
        float2 m0 = *(const float2*)(g_support + (long long)r0.x * F_OUT + lane * 2);
        float2 m1 = *(const float2*)(g_support + (long long)r1.x * F_OUT + lane * 2);
        float2 m2 = *(const float2*)(g_support + (long long)r2.x * F_OUT + lane * 2);
        float2 m3 = *(const float2*)(g_support + (long long)r3.x * F_OUT + lane * 2);
        float e0 = __int_as_float(r0.y), e1 = __int_as_float(r1.y);
        float e2 = __int_as_float(r2.y), e3 = __int_as_float(r3.y);
        acc.x = fmaf(e0, m0.x, acc.x);  acc.y = fmaf(e0, m0.y, acc.y);
        acc.x = fmaf(e1, m1.x, acc.x);  acc.y = fmaf(e1, m1.y, acc.y);
        acc.x = fmaf(e2, m2.x, acc.x);  acc.y = fmaf(e2, m2.y, acc.y);
        acc.x = fmaf(e3, m3.x, acc.x);  acc.y = fmaf(e3, m3.y, acc.y);
    }
    for (; j < deg; j++) {
        int2 r0 = g_edges[start + j];
        float2 m0 = *(const float2*)(g_support + (long long)r0.x * F_OUT + lane * 2);
        float e0 = __int_as_float(r0.y);
        acc.x = fmaf(e0, m0.x, acc.x);
        acc.y = fmaf(e0, m0.y, acc.y);
    }

    *(float2*)(out + (long long)node * F_OUT + lane * 2) = acc;
}

// ---------------------------------------------------------------------------
// Launch. GEMM (tensor-core) forked onto a side stream, overlapping the CSR
// build; join before gather. Stream/events cached; captured work identical
// every call.
//
// Inputs (metadata order):
//   0: x [N,128] f32  1: t [N] f32  2: src [E]  3: dst [E]
//   4: edge_vals [E] f32  5: weight [128,64] f32  6: bias [64] f32
// Output: [N,64] f32
// ---------------------------------------------------------------------------
extern "C" void kernel_launch(void* const* d_in, const int* in_sizes, int n_in,
                              void* d_out, int out_size)
{
    const float* x    = (const float*)d_in[0];
    const float* t    = (const float*)d_in[1];
    const void*  src  = d_in[2];
    const void*  dst  = d_in[3];
    const float* ev   = (const float*)d_in[4];
    const float* w    = (const float*)d_in[5];
    const float* bias = (const float*)d_in[6];
    float*       out  = (float*)d_out;

    const int n = in_sizes[1];   // N
    const int e = in_sizes[2];   // E

    static cudaStream_t s2 = nullptr;
    static cudaEvent_t  evFork = nullptr, evJoin = nullptr;
    if (!s2) {
        cudaStreamCreateWithFlags(&s2, cudaStreamNonBlocking);
        cudaEventCreateWithFlags(&evFork, cudaEventDisableTiming);
        cudaEventCreateWithFlags(&evJoin, cudaEventDisableTiming);
    }

    // ---- fork: GEMM branch (independent of edge processing) ----
    cudaEventRecord(evFork, 0);
    cudaStreamWaitEvent(s2, evFork, 0);
    gemm_tf32_kernel<<<(n + 63) / 64, 256, 0, s2>>>(x, w, t, n);
    cudaEventRecord(evJoin, s2);

    // ---- main branch: CSR build ----
    detect_zero_kernel<<<(n + 255) / 256, 256>>>((const long long*)src, n, e);

    int e4 = (e + 3) / 4;
    hist_kernel<<<(e4 + 255) / 256, 256>>>(dst, e);

    int nb = (n + 1023) / 1024;
    scan1_kernel<<<nb, 256>>>(n);
    scan3_kernel<<<(n + 255) / 256, 256>>>(n);

    reorder_kernel<<<(e4 + 255) / 256, 256>>>(src, dst, ev, e);

    // ---- join, then gather ----
    cudaStreamWaitEvent(0, evJoin, 0);
    gather_kernel<<<(n + 7) / 8, 256>>>(out, bias, n);
}